// round 2
// baseline (speedup 1.0000x reference)
#include <cuda_runtime.h>

#define C_IN   128
#define C_OUT  256
#define HH     56
#define WWID   56
#define HW     (HH*WWID)
#define NBATCH 32
#define NPIX   (NBATCH*HW)      // 100352
#define NTAP   9
#define KTOT   (NTAP*C_IN)      // 1152
#define BK     8
#define NITER  (KTOT/BK)        // 144

// scratch for transposed weights: [tap][cin][cout]
__device__ float g_wt[NTAP*C_IN*C_OUT];

__global__ void wtrans_kernel(const float* __restrict__ f) {
    int i = blockIdx.x * 256 + threadIdx.x;
    if (i < NTAP*C_IN*C_OUT) {
        int cout = i & 255;            // fastest
        int c    = (i >> 8) & 127;
        int tap  = i >> 15;
        // filters OIHW: f[((cout*C_IN + c)*3 + kh)*3 + kw] = f[(cout*C_IN+c)*9 + tap]
        g_wt[i] = f[(cout*C_IN + c)*9 + tap];
    }
}

__global__ __launch_bounds__(256, 2)
void conv_kernel(const float* __restrict__ in,
                 const float* __restrict__ bias,
                 float* __restrict__ out) {
    __shared__ float As[BK][128];   // couts
    __shared__ float Bs[BK][128];   // pixels

    const int tid = threadIdx.x;
    const int tx  = tid & 15;       // pixel dim of thread tile
    const int ty  = tid >> 4;       // cout dim of thread tile
    const int bx  = blockIdx.x;     // pixel block: 784
    const int by  = blockIdx.y;     // cout block: 2

    // loader coords: each thread loads 4 A + 4 B elements per BK tile
    const int lm = tid & 127;       // within-tile index (pixel for B, cout for A)
    const int lk = tid >> 7;        // 0/1 base k

    // per-thread pixel coords (fixed for all K iterations)
    const int pix = bx * 128 + lm;
    const int n   = pix / HW;
    const int rem = pix - n * HW;
    const int h   = rem / WWID;
    const int w   = rem - h * WWID;
    const int inBase = n * (C_IN * HW);
    const int coutA  = by * 128 + lm;

    float acc[8][8];
    #pragma unroll
    for (int i = 0; i < 8; ++i)
        #pragma unroll
        for (int j = 0; j < 8; ++j) acc[i][j] = 0.f;

    float aR[4], bR[4];

    auto load_tile = [&](int iter) {
        const int tap = iter >> 4;      // /16
        const int ck  = iter & 15;
        const int dh  = tap / 3 - 1;
        const int dw  = tap - (tap / 3) * 3 - 1;
        const int h2  = h + dh;
        const int w2  = w + dw;
        const bool valid = ((unsigned)h2 < (unsigned)HH) && ((unsigned)w2 < (unsigned)WWID);
        const int baddr = inBase + h2 * WWID + w2;
        const int c0 = ck * BK + lk;
        #pragma unroll
        for (int l = 0; l < 4; ++l) {
            const int c = c0 + l * 2;
            bR[l] = valid ? in[baddr + c * HW] : 0.f;
            aR[l] = g_wt[(tap * C_IN + c) * C_OUT + coutA];
        }
    };

    auto store_tile = [&]() {
        #pragma unroll
        for (int l = 0; l < 4; ++l) {
            As[lk + l * 2][lm] = aR[l];
            Bs[lk + l * 2][lm] = bR[l];
        }
    };

    load_tile(0);
    store_tile();
    __syncthreads();

    for (int iter = 0; iter < NITER; ++iter) {
        const bool more = (iter + 1 < NITER);
        if (more) load_tile(iter + 1);

        #pragma unroll
        for (int k = 0; k < BK; ++k) {
            float4 a0 = *reinterpret_cast<const float4*>(&As[k][ty * 8]);
            float4 a1 = *reinterpret_cast<const float4*>(&As[k][ty * 8 + 4]);
            float4 b0 = *reinterpret_cast<const float4*>(&Bs[k][tx * 8]);
            float4 b1 = *reinterpret_cast<const float4*>(&Bs[k][tx * 8 + 4]);
            float av[8] = {a0.x, a0.y, a0.z, a0.w, a1.x, a1.y, a1.z, a1.w};
            float bv[8] = {b0.x, b0.y, b0.z, b0.w, b1.x, b1.y, b1.z, b1.w};
            #pragma unroll
            for (int i = 0; i < 8; ++i)
                #pragma unroll
                for (int j = 0; j < 8; ++j)
                    acc[i][j] += av[i] * bv[j];
        }
        __syncthreads();
        if (more) {
            store_tile();
            __syncthreads();
        }
    }

    // epilogue: bias + coalesced float4 stores (pixels contiguous; 8-aligned
    // pixel groups never straddle an image boundary since 3136 % 8 == 0)
    const int p0  = bx * 128 + tx * 8;
    const int n2  = p0 / HW;
    const int off = p0 - n2 * HW;
    #pragma unroll
    for (int i = 0; i < 8; ++i) {
        const int cg = by * 128 + ty * 8 + i;
        const float bv = bias[cg];
        float* dst = out + (size_t)(n2 * C_OUT + cg) * HW + off;
        float4 v0 = make_float4(acc[i][0] + bv, acc[i][1] + bv,
                                acc[i][2] + bv, acc[i][3] + bv);
        float4 v1 = make_float4(acc[i][4] + bv, acc[i][5] + bv,
                                acc[i][6] + bv, acc[i][7] + bv);
        *reinterpret_cast<float4*>(dst)     = v0;
        *reinterpret_cast<float4*>(dst + 4) = v1;
    }
}

extern "C" void kernel_launch(void* const* d_in, const int* in_sizes, int n_in,
                              void* d_out, int out_size) {
    const float* in   = (const float*)d_in[0];
    const float* fl   = (const float*)d_in[1];
    const float* bias = (const float*)d_in[2];
    float* out        = (float*)d_out;

    wtrans_kernel<<<(NTAP*C_IN*C_OUT + 255) / 256, 256>>>(fl);

    dim3 grid(NPIX / 128, C_OUT / 128);
    conv_kernel<<<grid, 256>>>(in, bias, out);
}

// round 4
// speedup vs baseline: 2.3832x; 2.3832x over previous
#include <cuda_runtime.h>
#include <cstdint>

#define C_IN   128
#define C_OUT  256
#define HH     56
#define WW     56
#define HW     3136
#define NPIX   100352
#define KTOT   1152          // 9 taps * 128 cin (tap-major k)
#define BM     128
#define BN     256
#define BK     16
#define KTILES 72
#define TPB    256

// smem layout (32-bit words), fragment-native:
// A: [ks][mf(8)][lane(32)][4]  (+4 pad per ks)        -> conflict-free lds.128
// B: [ks][nf(32)][lane(32)][2] (nf stride padded 66)  -> conflict-free lds.64
#define A_KS_STRIDE 1028
#define A_WORDS     (2*A_KS_STRIDE)      // 2056
#define B_BASE      A_WORDS
#define B_NF_STRIDE 66
#define B_KS_STRIDE (32*B_NF_STRIDE)     // 2112
#define STG_WORDS   (A_WORDS + 2*B_KS_STRIDE)  // 6280
#define SMEM_BYTES  (2*STG_WORDS*4)      // 50240

// transposed weights: wt[cout][tap*128+cin]
__device__ float g_wt[C_OUT * KTOT];

__global__ void wtrans(const float* __restrict__ f) {
    int i = blockIdx.x * 256 + threadIdx.x;
    if (i < C_OUT * KTOT) {
        int cout = i / KTOT;
        int k    = i - cout * KTOT;
        int tap  = k >> 7;
        int cin  = k & 127;
        g_wt[i] = f[(cout * C_IN + cin) * 9 + tap];
    }
}

__device__ __forceinline__ uint32_t f2tf(float v) {
    uint32_t r;
    asm("cvt.rna.tf32.f32 %0, %1;" : "=r"(r) : "f"(v));
    return r;
}

__device__ __forceinline__ void mma_tf32(float* d, const uint32_t* a, const uint32_t* b) {
    asm volatile(
        "mma.sync.aligned.m16n8k8.row.col.f32.tf32.tf32.f32 "
        "{%0,%1,%2,%3}, {%4,%5,%6,%7}, {%8,%9}, {%0,%1,%2,%3};"
        : "+f"(d[0]), "+f"(d[1]), "+f"(d[2]), "+f"(d[3])
        : "r"(a[0]), "r"(a[1]), "r"(a[2]), "r"(a[3]), "r"(b[0]), "r"(b[1]));
}

__global__ __launch_bounds__(TPB, 1)
void conv_mma(const float* __restrict__ in, const float* __restrict__ bias,
              float* __restrict__ out) {
    extern __shared__ uint32_t sm[];
    const int tid  = threadIdx.x;
    const int warp = tid >> 5;
    const int lane = tid & 31;
    const int bx   = blockIdx.x;   // pixel block (392)
    const int by   = blockIdx.y;   // cout block (2)

    // ---------- producer constants ----------
    // B producer: thread = pixel
    const int pix = bx * BN + tid;
    const int n   = pix / HW;
    const int hw  = pix - n * HW;
    const int h   = hw / WW;
    const int w   = hw - h * WW;
    const float* inb = in + (size_t)n * C_IN * HW + h * WW + w;
    const int b_off0 = B_BASE + (tid >> 3) * B_NF_STRIDE + (tid & 7) * 8;

    // A producer: row = tid>>1 (cout within tile), khalf = tid&1
    const int ar  = tid >> 1;
    const int akh = tid & 1;
    const int amf = ar >> 4;
    const int arf = ar & 15;
    const int ag  = arf & 7;
    const int arb = arf >> 3;
    const int a_base = akh * A_KS_STRIDE + amf * 128 + ag * 16 + arb;
    const float* awp = g_wt + (size_t)(by * BM + ar) * KTOT + akh * 8;

    // ---------- consumer constants ----------
    const int wm = warp >> 2;   // 0..1 -> m offset 64
    const int wn = warp & 3;    // 0..3 -> n offset 64

    float acc[4][8][4];
    #pragma unroll
    for (int i = 0; i < 4; ++i)
        #pragma unroll
        for (int j = 0; j < 8; ++j)
            #pragma unroll
            for (int q = 0; q < 4; ++q) acc[i][j][q] = 0.f;

    uint32_t avr[8], bvr[16];

    auto load_tile = [&](int kt) {
        // A: 16 consecutive k of one cout row (this thread's half = 8)
        float4 a0 = *reinterpret_cast<const float4*>(awp + kt * BK);
        float4 a1 = *reinterpret_cast<const float4*>(awp + kt * BK + 4);
        avr[0] = f2tf(a0.x); avr[1] = f2tf(a0.y); avr[2] = f2tf(a0.z); avr[3] = f2tf(a0.w);
        avr[4] = f2tf(a1.x); avr[5] = f2tf(a1.y); avr[6] = f2tf(a1.z); avr[7] = f2tf(a1.w);
        // B: 16 cins of one tap for this thread's pixel
        const int tap  = kt >> 3;
        const int coff = (kt & 7) * 16;
        const int t3 = tap / 3;
        const int dh = t3 - 1, dw = tap - t3 * 3 - 1;
        const int h2 = h + dh, w2 = w + dw;
        const bool valid = ((unsigned)h2 < HH) && ((unsigned)w2 < WW);
        const float* ip = inb + dh * WW + dw + (size_t)coff * HW;
        #pragma unroll
        for (int c = 0; c < 16; ++c)
            bvr[c] = valid ? f2tf(ip[(size_t)c * HW]) : 0u;
    };

    auto store_tile = [&](int buf) {
        uint32_t* s = sm + buf * STG_WORDS;
        #pragma unroll
        for (int c = 0; c < 8; ++c) {
            const int t = c & 3, hc = c >> 2;
            s[a_base + t * 4 + 2 * hc] = avr[c];
        }
        #pragma unroll
        for (int k = 0; k < 16; ++k) {
            const int ks = k >> 3, kk = k & 7, t = kk & 3, jb = kk >> 2;
            s[b_off0 + ks * B_KS_STRIDE + t * 2 + jb] = bvr[k];
        }
    };

    auto mma_tile = [&](int buf) {
        const uint32_t* s = sm + buf * STG_WORDS;
        #pragma unroll
        for (int ks = 0; ks < 2; ++ks) {
            uint32_t a[4][4], b[8][2];
            #pragma unroll
            for (int i = 0; i < 4; ++i) {
                const int mf = wm * 4 + i;
                uint4 v = *reinterpret_cast<const uint4*>(
                    s + ks * A_KS_STRIDE + mf * 128 + lane * 4);
                a[i][0] = v.x; a[i][1] = v.y; a[i][2] = v.z; a[i][3] = v.w;
            }
            #pragma unroll
            for (int j = 0; j < 8; ++j) {
                const int nf = wn * 8 + j;
                uint2 v = *reinterpret_cast<const uint2*>(
                    s + B_BASE + ks * B_KS_STRIDE + nf * B_NF_STRIDE + lane * 2);
                b[j][0] = v.x; b[j][1] = v.y;
            }
            #pragma unroll
            for (int i = 0; i < 4; ++i)
                #pragma unroll
                for (int j = 0; j < 8; ++j)
                    mma_tf32(acc[i][j], a[i], b[j]);
        }
    };

    load_tile(0);
    store_tile(0);
    __syncthreads();

    for (int kt = 0; kt < KTILES; ++kt) {
        if (kt + 1 < KTILES) load_tile(kt + 1);
        mma_tile(kt & 1);
        if (kt + 1 < KTILES) store_tile((kt + 1) & 1);
        __syncthreads();
    }

    // ---------- epilogue: bias + float2 stores ----------
    const int eg = lane >> 2, et = lane & 3;
    #pragma unroll
    for (int i = 0; i < 4; ++i) {
        const int cout0 = by * BM + wm * 64 + i * 16 + eg;
        const float bz0 = bias[cout0];
        const float bz1 = bias[cout0 + 8];
        #pragma unroll
        for (int j = 0; j < 8; ++j) {
            const int pj  = bx * BN + wn * 64 + j * 8;       // 8-aligned, HW%8==0
            const int n2  = pj / HW;
            const int hw2 = pj - n2 * HW + et * 2;
            float2 v0 = make_float2(acc[i][j][0] + bz0, acc[i][j][1] + bz0);
            float2 v1 = make_float2(acc[i][j][2] + bz1, acc[i][j][3] + bz1);
            *reinterpret_cast<float2*>(out + ((size_t)(n2 * C_OUT + cout0))     * HW + hw2) = v0;
            *reinterpret_cast<float2*>(out + ((size_t)(n2 * C_OUT + cout0 + 8)) * HW + hw2) = v1;
        }
    }
}

extern "C" void kernel_launch(void* const* d_in, const int* in_sizes, int n_in,
                              void* d_out, int out_size) {
    const float* in   = (const float*)d_in[0];
    const float* fl   = (const float*)d_in[1];
    const float* bias = (const float*)d_in[2];
    float* out        = (float*)d_out;

    cudaFuncSetAttribute(conv_mma, cudaFuncAttributeMaxDynamicSharedMemorySize, SMEM_BYTES);

    wtrans<<<(C_OUT * KTOT + 255) / 256, 256>>>(fl);
    dim3 grid(NPIX / BN, C_OUT / BM);
    conv_mma<<<grid, TPB, SMEM_BYTES>>>(in, bias, out);
}

// round 5
// speedup vs baseline: 2.5083x; 1.0525x over previous
#include <cuda_runtime.h>
#include <cstdint>

#define C_IN   128
#define C_OUT  256
#define HH     56
#define WW     56
#define HW     3136
#define NPIX   100352
#define KTOT   1152          // 9 taps * 128 cin (tap-major k)
#define BM     128
#define BN     256
#define BK     16
#define KTILES 72
#define TPB    512

// smem layout (32-bit words), fragment-native:
// A: [ks][mf(8)][lane(32)][4]  (+4 pad per ks)        -> conflict-free lds.128
// B: [ks][nf(32)][lane(32)][2] (nf stride padded 66)  -> conflict-free lds.64
#define A_KS_STRIDE 1028
#define A_WORDS     (2*A_KS_STRIDE)      // 2056
#define B_BASE      A_WORDS
#define B_NF_STRIDE 66
#define B_KS_STRIDE (32*B_NF_STRIDE)     // 2112
#define STG_WORDS   (A_WORDS + 2*B_KS_STRIDE)  // 6280
#define SMEM_BYTES  (2*STG_WORDS*4)      // 50240

// transposed weights: wt[cout][tap*128+cin]
__device__ float g_wt[C_OUT * KTOT];

__global__ void wtrans(const float* __restrict__ f) {
    int i = blockIdx.x * 256 + threadIdx.x;
    if (i < C_OUT * KTOT) {
        int cout = i / KTOT;
        int k    = i - cout * KTOT;
        int tap  = k >> 7;
        int cin  = k & 127;
        g_wt[i] = f[(cout * C_IN + cin) * 9 + tap];
    }
}

__device__ __forceinline__ uint32_t f2tf(float v) {
    uint32_t r;
    asm("cvt.rna.tf32.f32 %0, %1;" : "=r"(r) : "f"(v));
    return r;
}

__device__ __forceinline__ void mma_tf32(float* d, const uint32_t* a, const uint32_t* b) {
    asm volatile(
        "mma.sync.aligned.m16n8k8.row.col.f32.tf32.tf32.f32 "
        "{%0,%1,%2,%3}, {%4,%5,%6,%7}, {%8,%9}, {%0,%1,%2,%3};"
        : "+f"(d[0]), "+f"(d[1]), "+f"(d[2]), "+f"(d[3])
        : "r"(a[0]), "r"(a[1]), "r"(a[2]), "r"(a[3]), "r"(b[0]), "r"(b[1]));
}

__global__ __launch_bounds__(TPB, 1)
void conv_mma(const float* __restrict__ in, const float* __restrict__ bias,
              float* __restrict__ out) {
    extern __shared__ uint32_t sm[];
    const int tid  = threadIdx.x;
    const int warp = tid >> 5;
    const int lane = tid & 31;
    const int bx   = blockIdx.x;   // pixel block (392)
    const int by   = blockIdx.y;   // cout block (2)
    const bool roleB = (tid < 256);

    // ---------- producer role B (warps 0-7): thread = pixel ----------
    const int pix = bx * BN + (tid & 255);
    const int n   = pix / HW;
    const int hw  = pix - n * HW;
    const int h   = hw / WW;
    const int w   = hw - h * WW;
    const float* inb = in + (size_t)n * C_IN * HW + h * WW + w;
    const int b_off0 = B_BASE + ((tid & 255) >> 3) * B_NF_STRIDE + (tid & 7) * 8;

    // ---------- producer role A (warps 8-15): t2 = tid-256 ----------
    const int t2  = tid & 255;
    const int ar  = t2 >> 1;          // cout row within tile
    const int akh = t2 & 1;           // k-half (ks)
    const int amf = ar >> 4;
    const int arf = ar & 15;
    const int ag  = arf & 7;
    const int arb = arf >> 3;
    const int a_base = akh * A_KS_STRIDE + amf * 128 + ag * 16 + arb;
    const float* awp = g_wt + (size_t)(by * BM + ar) * KTOT + akh * 8;

    // ---------- consumer constants: 16 warps = 4m x 4n, warp tile 32x64 ----------
    const int wm = warp >> 2;   // 0..3 -> m offset 32
    const int wn = warp & 3;    // 0..3 -> n offset 64

    float acc[2][8][4];
    #pragma unroll
    for (int i = 0; i < 2; ++i)
        #pragma unroll
        for (int j = 0; j < 8; ++j)
            #pragma unroll
            for (int q = 0; q < 4; ++q) acc[i][j][q] = 0.f;

    uint32_t avr[8], bvr[16];

    auto load_tile = [&](int kt) {
        if (roleB) {
            // B: 16 cins of one tap for this thread's pixel
            const int tap  = kt >> 3;
            const int coff = (kt & 7) * 16;
            const int t3 = tap / 3;
            const int dh = t3 - 1, dw = tap - t3 * 3 - 1;
            const int h2 = h + dh, w2 = w + dw;
            const bool valid = ((unsigned)h2 < HH) && ((unsigned)w2 < WW);
            const float* ip = inb + dh * WW + dw + (size_t)coff * HW;
            #pragma unroll
            for (int c = 0; c < 16; ++c)
                bvr[c] = valid ? f2tf(ip[(size_t)c * HW]) : 0u;
        } else {
            // A: 8 consecutive k of one cout row (this thread's ks half)
            float4 a0 = *reinterpret_cast<const float4*>(awp + kt * BK);
            float4 a1 = *reinterpret_cast<const float4*>(awp + kt * BK + 4);
            avr[0] = f2tf(a0.x); avr[1] = f2tf(a0.y); avr[2] = f2tf(a0.z); avr[3] = f2tf(a0.w);
            avr[4] = f2tf(a1.x); avr[5] = f2tf(a1.y); avr[6] = f2tf(a1.z); avr[7] = f2tf(a1.w);
        }
    };

    auto store_tile = [&](int buf) {
        uint32_t* s = sm + buf * STG_WORDS;
        if (roleB) {
            #pragma unroll
            for (int k = 0; k < 16; ++k) {
                const int ks = k >> 3, kk = k & 7, t = kk & 3, jb = kk >> 2;
                s[b_off0 + ks * B_KS_STRIDE + t * 2 + jb] = bvr[k];
            }
        } else {
            #pragma unroll
            for (int c = 0; c < 8; ++c) {
                const int t = c & 3, hc = c >> 2;
                s[a_base + t * 4 + 2 * hc] = avr[c];
            }
        }
    };

    auto mma_tile = [&](int buf) {
        const uint32_t* s = sm + buf * STG_WORDS;
        #pragma unroll
        for (int ks = 0; ks < 2; ++ks) {
            uint32_t a[2][4], b[8][2];
            #pragma unroll
            for (int i = 0; i < 2; ++i) {
                const int mf = wm * 2 + i;
                uint4 v = *reinterpret_cast<const uint4*>(
                    s + ks * A_KS_STRIDE + mf * 128 + lane * 4);
                a[i][0] = v.x; a[i][1] = v.y; a[i][2] = v.z; a[i][3] = v.w;
            }
            #pragma unroll
            for (int j = 0; j < 8; ++j) {
                const int nf = wn * 8 + j;
                uint2 v = *reinterpret_cast<const uint2*>(
                    s + B_BASE + ks * B_KS_STRIDE + nf * B_NF_STRIDE + lane * 2);
                b[j][0] = v.x; b[j][1] = v.y;
            }
            #pragma unroll
            for (int i = 0; i < 2; ++i)
                #pragma unroll
                for (int j = 0; j < 8; ++j)
                    mma_tf32(acc[i][j], a[i], b[j]);
        }
    };

    load_tile(0);
    store_tile(0);
    __syncthreads();

    for (int kt = 0; kt < KTILES; ++kt) {
        if (kt + 1 < KTILES) load_tile(kt + 1);
        mma_tile(kt & 1);
        if (kt + 1 < KTILES) store_tile((kt + 1) & 1);
        __syncthreads();
    }

    // ---------- epilogue: bias + float2 stores ----------
    const int eg = lane >> 2, et = lane & 3;
    #pragma unroll
    for (int i = 0; i < 2; ++i) {
        const int cout0 = by * BM + wm * 32 + i * 16 + eg;
        const float bz0 = bias[cout0];
        const float bz1 = bias[cout0 + 8];
        #pragma unroll
        for (int j = 0; j < 8; ++j) {
            const int pj  = bx * BN + wn * 64 + j * 8;       // 8-aligned, HW%8==0
            const int n2  = pj / HW;
            const int hw2 = pj - n2 * HW + et * 2;
            float2 v0 = make_float2(acc[i][j][0] + bz0, acc[i][j][1] + bz0);
            float2 v1 = make_float2(acc[i][j][2] + bz1, acc[i][j][3] + bz1);
            *reinterpret_cast<float2*>(out + ((size_t)(n2 * C_OUT + cout0))     * HW + hw2) = v0;
            *reinterpret_cast<float2*>(out + ((size_t)(n2 * C_OUT + cout0 + 8)) * HW + hw2) = v1;
        }
    }
}

extern "C" void kernel_launch(void* const* d_in, const int* in_sizes, int n_in,
                              void* d_out, int out_size) {
    const float* in   = (const float*)d_in[0];
    const float* fl   = (const float*)d_in[1];
    const float* bias = (const float*)d_in[2];
    float* out        = (float*)d_out;

    cudaFuncSetAttribute(conv_mma, cudaFuncAttributeMaxDynamicSharedMemorySize, SMEM_BYTES);

    wtrans<<<(C_OUT * KTOT + 255) / 256, 256>>>(fl);
    dim3 grid(NPIX / BN, C_OUT / BM);
    conv_mma<<<grid, TPB, SMEM_BYTES>>>(in, bias, out);
}

// round 6
// speedup vs baseline: 3.3264x; 1.3261x over previous
#include <cuda_runtime.h>
#include <cstdint>

#define C_IN   128
#define C_OUT  256
#define HH     56
#define WW     56
#define HW     3136
#define NPIX   100352
#define KTOT   1152          // 9 taps * 128 cin (tap-major k)
#define BM     128
#define BN     256
#define BK     16
#define KTILES 72
#define TPB    512
#define STAGES 5

// smem (u32 words) per stage:
// A: [ks(2)][mf(8)][lane(32)][4]  stride 1028/ks  -> lds.128 conflict-free
// B: [pixel(256)][16] pixel stride 24             -> lds.64 conflict-free
#define A_KS_STRIDE 1028
#define A_WORDS     2056
#define B_BASE      2056
#define B_PIX       24
#define STG_WORDS   (A_WORDS + 256*B_PIX)      // 8200
#define SMEM_BYTES  (STAGES*STG_WORDS*4)       // 164000

// scratch: A in fragment-native tf32 layout, input in NHWC pi-permuted tf32
__device__ uint32_t g_wa[2*KTILES*512*4];            // 1.18 MB
__device__ uint32_t g_in2[(size_t)NPIX*C_IN];        // 51.4 MB

__device__ __forceinline__ uint32_t f2tf(float v) {
    uint32_t r;
    asm("cvt.rna.tf32.f32 %0, %1;" : "=r"(r) : "f"(v));
    return r;
}

// weights -> fragment-native tf32
__global__ void twa(const float* __restrict__ f) {
    int idx = blockIdx.x * 256 + threadIdx.x;
    if (idx >= 2*KTILES*512*4) return;
    int reg  = idx & 3;
    int lane = (idx >> 2) & 31;
    int mf   = (idx >> 7) & 7;
    int ks   = (idx >> 10) & 1;
    int r4   = idx >> 11;
    int kt   = r4 % KTILES;
    int by   = r4 / KTILES;
    int cout = by*128 + mf*16 + (lane >> 2) + 8*(reg & 1);
    int k    = kt*16 + ks*8 + (lane & 3) + 4*(reg >> 1);
    int tap  = k >> 7, cin = k & 127;
    g_wa[idx] = f2tf(f[(cout*C_IN + cin)*9 + tap]);
}

// input NCHW -> NHWC tf32 with pi-permuted cin (pos = (c&~7) + (c&3)*2 + ((c>>2)&1))
__global__ void tin(const float* __restrict__ in) {
    __shared__ float t[32][33];
    const int hw0 = blockIdx.x * 32, c0 = blockIdx.y * 32, n = blockIdx.z;
    const int tx = threadIdx.x, ty = threadIdx.y;
    const float* p = in + ((size_t)n*C_IN + c0)*HW + hw0;
    #pragma unroll
    for (int i = 0; i < 4; ++i)
        t[ty + 8*i][tx] = p[(size_t)(ty + 8*i)*HW + tx];
    __syncthreads();
    const int posloc = (tx & ~7) + (tx & 3)*2 + ((tx >> 2) & 1);
    #pragma unroll
    for (int i = 0; i < 4; ++i) {
        int pix = ty + 8*i;
        g_in2[((size_t)(n*HW + hw0 + pix))*C_IN + c0 + posloc] = f2tf(t[tx][pix]);
    }
}

__device__ __forceinline__ uint32_t s2u(const void* p) {
    uint32_t a;
    asm("{ .reg .u64 t; cvta.to.shared.u64 t, %1; cvt.u32.u64 %0, t; }" : "=r"(a) : "l"(p));
    return a;
}
__device__ __forceinline__ void cp16(uint32_t dst, const void* src, uint32_t sz) {
    asm volatile("cp.async.cg.shared.global [%0], [%1], 16, %2;"
                 :: "r"(dst), "l"(src), "r"(sz));
}
__device__ __forceinline__ void mma_tf32(float* d, const uint32_t* a, const uint32_t* b) {
    asm volatile(
        "mma.sync.aligned.m16n8k8.row.col.f32.tf32.tf32.f32 "
        "{%0,%1,%2,%3}, {%4,%5,%6,%7}, {%8,%9}, {%0,%1,%2,%3};"
        : "+f"(d[0]), "+f"(d[1]), "+f"(d[2]), "+f"(d[3])
        : "r"(a[0]), "r"(a[1]), "r"(a[2]), "r"(a[3]), "r"(b[0]), "r"(b[1]));
}

__global__ __launch_bounds__(TPB, 1)
void conv_mma(const float* __restrict__ bias, float* __restrict__ out) {
    extern __shared__ uint32_t sm[];
    const uint32_t sb = s2u(sm);
    const int tid  = threadIdx.x;
    const int warp = tid >> 5;
    const int lane = tid & 31;
    const int bx   = blockIdx.x;   // pixel block (392)
    const int by   = blockIdx.y;   // cout block (2)

    // ---- A copy: thread = chunk (ks,mf,lane) ----
    const uint32_t a_dst = ((tid >> 8) * A_KS_STRIDE + ((tid >> 5) & 7) * 128 + (tid & 31) * 4) * 4;
    const uint32_t* a_src0 = g_wa + ((size_t)by * KTILES * 512 + tid) * 4;

    // ---- B copy: chunks tid and tid+512 -> pixels p0, p0+128, kq = tid&3 ----
    const int p0  = tid >> 2;
    const int kq  = tid & 3;
    const int pixA = bx * BN + p0;
    const int pixB = pixA + 128;
    const int nA = pixA / HW, hwA = pixA - nA * HW, hA = hwA / WW, wA = hwA - hA * WW;
    const int nB = pixB / HW, hwB = pixB - nB * HW, hB = hwB / WW, wB = hwB - hB * WW;
    const uint32_t bdstA = (B_BASE + p0 * B_PIX + kq * 4) * 4;
    const uint32_t bdstB = bdstA + 128 * B_PIX * 4;

    // ---- consumer: 16 warps, 4m x 4n, warp tile 32x64 ----
    const int wm = warp >> 2, wn = warp & 3;

    float acc[2][8][4];
    #pragma unroll
    for (int i = 0; i < 2; ++i)
        #pragma unroll
        for (int j = 0; j < 8; ++j)
            #pragma unroll
            for (int q = 0; q < 4; ++q) acc[i][j][q] = 0.f;

    auto issue_copy = [&](int kt, int stg) {
        const uint32_t s0 = sb + stg * (STG_WORDS * 4);
        cp16(s0 + a_dst, a_src0 + (size_t)kt * 2048, 16);
        const int tap = kt >> 3;
        const int t3  = tap / 3;
        const int dh  = t3 - 1, dw = tap - t3 * 3 - 1;
        const int coff = (kt & 7) * 16 + kq * 4;
        {
            const bool v = ((unsigned)(hA + dh) < HH) && ((unsigned)(wA + dw) < WW);
            const uint32_t* src = g_in2 + (size_t)(pixA + dh * WW + dw) * C_IN + coff;
            cp16(s0 + bdstA, src, v ? 16u : 0u);
        }
        {
            const bool v = ((unsigned)(hB + dh) < HH) && ((unsigned)(wB + dw) < WW);
            const uint32_t* src = g_in2 + (size_t)(pixB + dh * WW + dw) * C_IN + coff;
            cp16(s0 + bdstB, src, v ? 16u : 0u);
        }
    };

    auto mma_tile = [&](int stg) {
        const uint32_t* s = sm + stg * STG_WORDS;
        #pragma unroll
        for (int ks = 0; ks < 2; ++ks) {
            uint32_t a[2][4];
            uint32_t b[8][2];
            #pragma unroll
            for (int i = 0; i < 2; ++i) {
                uint4 v = *reinterpret_cast<const uint4*>(
                    s + ks * A_KS_STRIDE + (wm * 2 + i) * 128 + lane * 4);
                a[i][0] = v.x; a[i][1] = v.y; a[i][2] = v.z; a[i][3] = v.w;
            }
            #pragma unroll
            for (int j = 0; j < 8; ++j) {
                uint2 v = *reinterpret_cast<const uint2*>(
                    s + B_BASE + (wn * 64 + j * 8 + (lane >> 2)) * B_PIX + ks * 8 + (lane & 3) * 2);
                b[j][0] = v.x; b[j][1] = v.y;
            }
            #pragma unroll
            for (int i = 0; i < 2; ++i)
                #pragma unroll
                for (int j = 0; j < 8; ++j)
                    mma_tf32(acc[i][j], a[i], b[j]);
        }
    };

    #pragma unroll
    for (int s = 0; s < STAGES - 1; ++s) {
        issue_copy(s, s);
        asm volatile("cp.async.commit_group;" ::: "memory");
    }

    int stg = 0;
    for (int kt = 0; kt < KTILES; ++kt) {
        asm volatile("cp.async.wait_group 3;" ::: "memory");
        __syncthreads();
        mma_tile(stg);
        if (kt + STAGES - 1 < KTILES) {
            int ns = stg + STAGES - 1;
            if (ns >= STAGES) ns -= STAGES;
            issue_copy(kt + STAGES - 1, ns);
        }
        asm volatile("cp.async.commit_group;" ::: "memory");
        if (++stg == STAGES) stg = 0;
    }

    // ---- epilogue: bias + float2 stores ----
    const int eg = lane >> 2, et = lane & 3;
    #pragma unroll
    for (int i = 0; i < 2; ++i) {
        const int cout0 = by * BM + wm * 32 + i * 16 + eg;
        const float bz0 = bias[cout0];
        const float bz1 = bias[cout0 + 8];
        #pragma unroll
        for (int j = 0; j < 8; ++j) {
            const int pj  = bx * BN + wn * 64 + j * 8;       // 8-aligned, HW%8==0
            const int n2  = pj / HW;
            const int hw2 = pj - n2 * HW + et * 2;
            float2 v0 = make_float2(acc[i][j][0] + bz0, acc[i][j][1] + bz0);
            float2 v1 = make_float2(acc[i][j][2] + bz1, acc[i][j][3] + bz1);
            *reinterpret_cast<float2*>(out + ((size_t)(n2 * C_OUT + cout0))     * HW + hw2) = v0;
            *reinterpret_cast<float2*>(out + ((size_t)(n2 * C_OUT + cout0 + 8)) * HW + hw2) = v1;
        }
    }
}

extern "C" void kernel_launch(void* const* d_in, const int* in_sizes, int n_in,
                              void* d_out, int out_size) {
    const float* in   = (const float*)d_in[0];
    const float* fl   = (const float*)d_in[1];
    const float* bias = (const float*)d_in[2];
    float* out        = (float*)d_out;

    cudaFuncSetAttribute(conv_mma, cudaFuncAttributeMaxDynamicSharedMemorySize, SMEM_BYTES);

    twa<<<(2*KTILES*512*4 + 255) / 256, 256>>>(fl);
    dim3 tg(HW / 32, C_IN / 32, 32);
    tin<<<tg, dim3(32, 8)>>>(in);
    dim3 grid(NPIX / BN, C_OUT / BM);
    conv_mma<<<grid, TPB, SMEM_BYTES>>>(bias, out);
}

// round 7
// speedup vs baseline: 3.7399x; 1.1243x over previous
#include <cuda_runtime.h>
#include <cstdint>

#define C_IN   128
#define C_OUT  256
#define HH     56
#define WW     56
#define HW     3136
#define NPIX   100352
#define KTOT   1152          // 9 taps * 128 cin (tap-major k)
#define BM     128
#define BN     256
#define BK     16
#define KTILES 72
#define TPB    512
#define STAGES 6

// smem: B only. [pixel(256)][16 words] (64B/pixel, no pad)
#define STG_WORDS   4096
#define SMEM_BYTES  (STAGES*STG_WORDS*4)     // 98304

// scratch: A in fragment-native tf32 layout, input in NHWC pi-permuted tf32
__device__ uint32_t g_wa[2*KTILES*512*4];            // 1.18 MB
__device__ uint32_t g_in2[(size_t)NPIX*C_IN];        // 51.4 MB

__device__ __forceinline__ uint32_t f2tf(float v) {
    uint32_t r;
    asm("cvt.rna.tf32.f32 %0, %1;" : "=r"(r) : "f"(v));
    return r;
}

// weights -> fragment-native tf32: word = (by*KT+kt)*2048 + ks*1024 + mf*128 + lane*4 + reg
// k = kt*16 + ks*8 + jb*4 + t   (t = lane&3, jb = reg>>1), cout = mf*16 + (lane>>2) + 8*(reg&1)
__global__ void twa(const float* __restrict__ f) {
    int idx = blockIdx.x * 256 + threadIdx.x;
    if (idx >= 2*KTILES*512*4) return;
    int reg  = idx & 3;
    int lane = (idx >> 2) & 31;
    int mf   = (idx >> 7) & 7;
    int ks   = (idx >> 10) & 1;
    int r4   = idx >> 11;
    int kt   = r4 % KTILES;
    int by   = r4 / KTILES;
    int cout = by*128 + mf*16 + (lane >> 2) + 8*(reg & 1);
    int k    = kt*16 + ks*8 + (lane & 3) + 4*(reg >> 1);
    int tap  = k >> 7, cin = k & 127;
    g_wa[idx] = f2tf(f[(cout*C_IN + cin)*9 + tap]);
}

// input NCHW -> NHWC tf32, cin pi-permuted within each 16-group:
// pos = (c&~15) + 4*(c&3) + 2*((c>>3)&1) + ((c>>2)&1)
__global__ void tin(const float* __restrict__ in) {
    __shared__ float t[32][33];
    const int hw0 = blockIdx.x * 32, c0 = blockIdx.y * 32, n = blockIdx.z;
    const int tx = threadIdx.x, ty = threadIdx.y;
    const float* p = in + ((size_t)n*C_IN + c0)*HW + hw0;
    #pragma unroll
    for (int i = 0; i < 4; ++i)
        t[ty + 8*i][tx] = p[(size_t)(ty + 8*i)*HW + tx];
    __syncthreads();
    const int posloc = (tx & 16) + 4*(tx & 3) + 2*((tx >> 3) & 1) + ((tx >> 2) & 1);
    #pragma unroll
    for (int i = 0; i < 4; ++i) {
        int pix = ty + 8*i;
        g_in2[((size_t)(n*HW + hw0 + pix))*C_IN + c0 + posloc] = f2tf(t[tx][pix]);
    }
}

__device__ __forceinline__ uint32_t s2u(const void* p) {
    uint32_t a;
    asm("{ .reg .u64 t; cvta.to.shared.u64 t, %1; cvt.u32.u64 %0, t; }" : "=r"(a) : "l"(p));
    return a;
}
__device__ __forceinline__ void cp16(uint32_t dst, const void* src, uint32_t sz) {
    asm volatile("cp.async.cg.shared.global [%0], [%1], 16, %2;"
                 :: "r"(dst), "l"(src), "r"(sz));
}
__device__ __forceinline__ void mma_tf32(float* d, const uint32_t* a,
                                         uint32_t b0, uint32_t b1) {
    asm volatile(
        "mma.sync.aligned.m16n8k8.row.col.f32.tf32.tf32.f32 "
        "{%0,%1,%2,%3}, {%4,%5,%6,%7}, {%8,%9}, {%0,%1,%2,%3};"
        : "+f"(d[0]), "+f"(d[1]), "+f"(d[2]), "+f"(d[3])
        : "r"(a[0]), "r"(a[1]), "r"(a[2]), "r"(a[3]), "r"(b0), "r"(b1));
}

__global__ __launch_bounds__(TPB, 1)
void conv_mma(const float* __restrict__ bias, float* __restrict__ out) {
    extern __shared__ uint32_t sm[];
    const uint32_t sb = s2u(sm);
    const int tid  = threadIdx.x;
    const int warp = tid >> 5;
    const int lane = tid & 31;
    const int bx   = blockIdx.x;   // pixel block (392)
    const int by   = blockIdx.y;   // cout block (2)

    // ---- B copy: thread handles pixels p0 and p0+128, 16B chunk kq ----
    const int p0  = tid >> 2;
    const int kq  = tid & 3;
    const int pixA = bx * BN + p0;
    const int pixB = pixA + 128;
    const int nA = pixA / HW, hwA = pixA - nA * HW, hA = hwA / WW, wA = hwA - hA * WW;
    const int nB = pixB / HW, hwB = pixB - nB * HW, hB = hwB / WW, wB = hwB - hB * WW;
    const uint32_t bdstA = (p0 * 16 + kq * 4) * 4;
    const uint32_t bdstB = bdstA + 128 * 16 * 4;

    // ---- consumer: 16 warps, 4m x 4n, warp tile 32x64 ----
    const int wm = warp >> 2, wn = warp & 3;
    // A fragment gmem base (fragment-native): + kt*2048 + ks*1024 + (wm*2+i)*128 + lane*4
    const uint32_t* a_gm = g_wa + (size_t)by * (KTILES * 2048) + (wm * 2) * 128 + lane * 4;

    float acc[2][8][4];
    #pragma unroll
    for (int i = 0; i < 2; ++i)
        #pragma unroll
        for (int j = 0; j < 8; ++j)
            #pragma unroll
            for (int q = 0; q < 4; ++q) acc[i][j][q] = 0.f;

    auto issue_copy = [&](int kt, int stg) {
        const uint32_t s0 = sb + stg * (STG_WORDS * 4);
        const int tap = kt >> 3;
        const int t3  = tap / 3;
        const int dh  = t3 - 1, dw = tap - t3 * 3 - 1;
        const int coff = (kt & 7) * 16 + kq * 4;
        {
            const bool v = ((unsigned)(hA + dh) < HH) && ((unsigned)(wA + dw) < WW);
            const uint32_t* src = g_in2 + (size_t)(pixA + dh * WW + dw) * C_IN + coff;
            cp16(s0 + bdstA, src, v ? 16u : 0u);
        }
        {
            const bool v = ((unsigned)(hB + dh) < HH) && ((unsigned)(wB + dw) < WW);
            const uint32_t* src = g_in2 + (size_t)(pixB + dh * WW + dw) * C_IN + coff;
            cp16(s0 + bdstB, src, v ? 16u : 0u);
        }
    };

    #pragma unroll
    for (int s = 0; s < STAGES - 1; ++s) {
        issue_copy(s, s);
        asm volatile("cp.async.commit_group;" ::: "memory");
    }

    // prefetch A fragments for tile 0
    uint4 aN[2][2];   // [i][ks]
    #pragma unroll
    for (int i = 0; i < 2; ++i)
        #pragma unroll
        for (int ks = 0; ks < 2; ++ks)
            aN[i][ks] = *reinterpret_cast<const uint4*>(a_gm + ks * 1024 + i * 128);

    const int b_off = (wn * 64 + (lane >> 2)) * 16 + (lane & 3) * 4;

    int stg = 0;
    for (int kt = 0; kt < KTILES; ++kt) {
        asm volatile("cp.async.wait_group 4;" ::: "memory");
        __syncthreads();

        uint32_t aw[2][2][4];
        #pragma unroll
        for (int i = 0; i < 2; ++i)
            #pragma unroll
            for (int ks = 0; ks < 2; ++ks) {
                aw[i][ks][0] = aN[i][ks].x; aw[i][ks][1] = aN[i][ks].y;
                aw[i][ks][2] = aN[i][ks].z; aw[i][ks][3] = aN[i][ks].w;
            }
        if (kt + 1 < KTILES) {
            const uint32_t* ap = a_gm + (size_t)(kt + 1) * 2048;
            #pragma unroll
            for (int i = 0; i < 2; ++i)
                #pragma unroll
                for (int ks = 0; ks < 2; ++ks)
                    aN[i][ks] = *reinterpret_cast<const uint4*>(ap + ks * 1024 + i * 128);
        }

        const uint32_t* s = sm + stg * STG_WORDS;
        #pragma unroll
        for (int j = 0; j < 8; ++j) {
            uint4 bv = *reinterpret_cast<const uint4*>(s + b_off + j * 128);
            mma_tf32(acc[0][j], aw[0][0], bv.x, bv.y);
            mma_tf32(acc[1][j], aw[1][0], bv.x, bv.y);
            mma_tf32(acc[0][j], aw[0][1], bv.z, bv.w);
            mma_tf32(acc[1][j], aw[1][1], bv.z, bv.w);
        }

        if (kt + STAGES - 1 < KTILES) {
            int ns = stg + STAGES - 1;
            if (ns >= STAGES) ns -= STAGES;
            issue_copy(kt + STAGES - 1, ns);
        }
        asm volatile("cp.async.commit_group;" ::: "memory");
        if (++stg == STAGES) stg = 0;
    }

    // ---- epilogue: bias + float2 stores ----
    const int eg = lane >> 2, et = lane & 3;
    #pragma unroll
    for (int i = 0; i < 2; ++i) {
        const int cout0 = by * BM + wm * 32 + i * 16 + eg;
        const float bz0 = bias[cout0];
        const float bz1 = bias[cout0 + 8];
        #pragma unroll
        for (int j = 0; j < 8; ++j) {
            const int pj  = bx * BN + wn * 64 + j * 8;       // 8-aligned, HW%8==0
            const int n2  = pj / HW;
            const int hw2 = pj - n2 * HW + et * 2;
            float2 v0 = make_float2(acc[i][j][0] + bz0, acc[i][j][1] + bz0);
            float2 v1 = make_float2(acc[i][j][2] + bz1, acc[i][j][3] + bz1);
            *reinterpret_cast<float2*>(out + ((size_t)(n2 * C_OUT + cout0))     * HW + hw2) = v0;
            *reinterpret_cast<float2*>(out + ((size_t)(n2 * C_OUT + cout0 + 8)) * HW + hw2) = v1;
        }
    }
}

extern "C" void kernel_launch(void* const* d_in, const int* in_sizes, int n_in,
                              void* d_out, int out_size) {
    const float* in   = (const float*)d_in[0];
    const float* fl   = (const float*)d_in[1];
    const float* bias = (const float*)d_in[2];
    float* out        = (float*)d_out;

    cudaFuncSetAttribute(conv_mma, cudaFuncAttributeMaxDynamicSharedMemorySize, SMEM_BYTES);

    twa<<<(2*KTILES*512*4 + 255) / 256, 256>>>(fl);
    dim3 tg(HW / 32, C_IN / 32, 32);
    tin<<<tg, dim3(32, 8)>>>(in);
    dim3 grid(NPIX / BN, C_OUT / BM);
    conv_mma<<<grid, TPB, SMEM_BYTES>>>(bias, out);
}

// round 8
// speedup vs baseline: 4.3077x; 1.1518x over previous
#include <cuda_runtime.h>
#include <cstdint>

#define C_IN   128
#define C_OUT  256
#define HH     56
#define WW     56
#define HW     3136
#define NPIX   100352
#define KTOT   1152          // 9 taps * 128 cin (tap-major k)
#define BM     128
#define BN     128
#define BK     16
#define KTILES 72
#define TPB    256
#define STAGES 6

// smem: B only. [pixel(128)][16 words] (64B/pixel)
#define STG_WORDS   2048
#define SMEM_BYTES  (STAGES*STG_WORDS*4)     // 49152

// scratch: A in fragment-native tf32 layout, input in NHWC pi-permuted tf32
__device__ uint32_t g_wa[2*KTILES*512*4];            // 1.18 MB
__device__ uint32_t g_in2[(size_t)NPIX*C_IN];        // 51.4 MB

__device__ __forceinline__ uint32_t f2tf(float v) {
    uint32_t r;
    asm("cvt.rna.tf32.f32 %0, %1;" : "=r"(r) : "f"(v));
    return r;
}

// weights -> fragment-native tf32: word = (by*KT+kt)*2048 + ks*1024 + mf*128 + lane*4 + reg
__global__ void twa(const float* __restrict__ f) {
    int idx = blockIdx.x * 256 + threadIdx.x;
    if (idx >= 2*KTILES*512*4) return;
    int reg  = idx & 3;
    int lane = (idx >> 2) & 31;
    int mf   = (idx >> 7) & 7;
    int ks   = (idx >> 10) & 1;
    int r4   = idx >> 11;
    int kt   = r4 % KTILES;
    int by   = r4 / KTILES;
    int cout = by*128 + mf*16 + (lane >> 2) + 8*(reg & 1);
    int k    = kt*16 + ks*8 + (lane & 3) + 4*(reg >> 1);
    int tap  = k >> 7, cin = k & 127;
    g_wa[idx] = f2tf(f[(cout*C_IN + cin)*9 + tap]);
}

// input NCHW -> NHWC tf32, cin pi-permuted within each 16-group:
// pos = (c&~15) + 4*(c&3) + 2*((c>>3)&1) + ((c>>2)&1)
__global__ void tin(const float* __restrict__ in) {
    __shared__ float t[32][33];
    const int hw0 = blockIdx.x * 32, c0 = blockIdx.y * 32, n = blockIdx.z;
    const int tx = threadIdx.x, ty = threadIdx.y;
    const float* p = in + ((size_t)n*C_IN + c0)*HW + hw0;
    #pragma unroll
    for (int i = 0; i < 4; ++i)
        t[ty + 8*i][tx] = p[(size_t)(ty + 8*i)*HW + tx];
    __syncthreads();
    const int posloc = (tx & 16) + 4*(tx & 3) + 2*((tx >> 3) & 1) + ((tx >> 2) & 1);
    #pragma unroll
    for (int i = 0; i < 4; ++i) {
        int pix = ty + 8*i;
        g_in2[((size_t)(n*HW + hw0 + pix))*C_IN + c0 + posloc] = f2tf(t[tx][pix]);
    }
}

__device__ __forceinline__ uint32_t s2u(const void* p) {
    uint32_t a;
    asm("{ .reg .u64 t; cvta.to.shared.u64 t, %1; cvt.u32.u64 %0, t; }" : "=r"(a) : "l"(p));
    return a;
}
__device__ __forceinline__ void cp16(uint32_t dst, const void* src, uint32_t sz) {
    asm volatile("cp.async.cg.shared.global [%0], [%1], 16, %2;"
                 :: "r"(dst), "l"(src), "r"(sz));
}
__device__ __forceinline__ void mma_tf32(float* d, const uint32_t* a,
                                         uint32_t b0, uint32_t b1) {
    asm volatile(
        "mma.sync.aligned.m16n8k8.row.col.f32.tf32.tf32.f32 "
        "{%0,%1,%2,%3}, {%4,%5,%6,%7}, {%8,%9}, {%0,%1,%2,%3};"
        : "+f"(d[0]), "+f"(d[1]), "+f"(d[2]), "+f"(d[3])
        : "r"(a[0]), "r"(a[1]), "r"(a[2]), "r"(a[3]), "r"(b0), "r"(b1));
}

__global__ __launch_bounds__(TPB, 2)
void conv_mma(const float* __restrict__ bias, float* __restrict__ out) {
    extern __shared__ uint32_t sm[];
    const uint32_t sb = s2u(sm);
    const int tid  = threadIdx.x;
    const int warp = tid >> 5;
    const int lane = tid & 31;
    const int bx   = blockIdx.x;   // pixel block (784)
    const int by   = blockIdx.y;   // cout block (2)

    // ---- B copy: thread = pixel p0, two 16B chunks ----
    const int p0  = tid >> 1;
    const int kq  = (tid & 1) * 2;      // chunk pair base
    const int pix = bx * BN + p0;
    const int n   = pix / HW;
    const int hw  = pix - n * HW;
    const int h   = hw / WW;
    const int w   = hw - h * WW;
    const uint32_t bdst = (p0 * 16 + kq * 4) * 4;

    // ---- consumer: 8 warps, 4m x 2n, warp tile 32x64 ----
    const int wm = warp >> 1, wn = warp & 1;
    const uint32_t* a_gm = g_wa + (size_t)by * (KTILES * 2048) + (wm * 2) * 128 + lane * 4;

    float acc[2][8][4];
    #pragma unroll
    for (int i = 0; i < 2; ++i)
        #pragma unroll
        for (int j = 0; j < 8; ++j)
            #pragma unroll
            for (int q = 0; q < 4; ++q) acc[i][j][q] = 0.f;

    auto issue_copy = [&](int kt, int stg) {
        const uint32_t s0 = sb + stg * (STG_WORDS * 4);
        const int tap = kt >> 3;
        const int t3  = tap / 3;
        const int dh  = t3 - 1, dw = tap - t3 * 3 - 1;
        const bool v = ((unsigned)(h + dh) < HH) && ((unsigned)(w + dw) < WW);
        const uint32_t sz = v ? 16u : 0u;
        const int coff = (kt & 7) * 16 + kq * 4;
        const uint32_t* src = g_in2 + (size_t)(pix + dh * WW + dw) * C_IN + coff;
        cp16(s0 + bdst,      src,     sz);
        cp16(s0 + bdst + 16, src + 4, sz);
    };

    #pragma unroll
    for (int s = 0; s < STAGES - 1; ++s) {
        issue_copy(s, s);
        asm volatile("cp.async.commit_group;" ::: "memory");
    }

    // prefetch A fragments for tile 0
    uint4 aN[2][2];   // [i][ks]
    #pragma unroll
    for (int i = 0; i < 2; ++i)
        #pragma unroll
        for (int ks = 0; ks < 2; ++ks)
            aN[i][ks] = *reinterpret_cast<const uint4*>(a_gm + ks * 1024 + i * 128);

    const int b_off = (wn * 64 + (lane >> 2)) * 16 + (lane & 3) * 4;

    int stg = 0;
    for (int kt = 0; kt < KTILES; ++kt) {
        asm volatile("cp.async.wait_group 4;" ::: "memory");
        __syncthreads();

        uint32_t aw[2][2][4];
        #pragma unroll
        for (int i = 0; i < 2; ++i)
            #pragma unroll
            for (int ks = 0; ks < 2; ++ks) {
                aw[i][ks][0] = aN[i][ks].x; aw[i][ks][1] = aN[i][ks].y;
                aw[i][ks][2] = aN[i][ks].z; aw[i][ks][3] = aN[i][ks].w;
            }
        if (kt + 1 < KTILES) {
            const uint32_t* ap = a_gm + (size_t)(kt + 1) * 2048;
            #pragma unroll
            for (int i = 0; i < 2; ++i)
                #pragma unroll
                for (int ks = 0; ks < 2; ++ks)
                    aN[i][ks] = *reinterpret_cast<const uint4*>(ap + ks * 1024 + i * 128);
        }

        const uint32_t* s = sm + stg * STG_WORDS;
        #pragma unroll
        for (int j = 0; j < 8; ++j) {
            uint4 bv = *reinterpret_cast<const uint4*>(s + b_off + j * 128);
            mma_tf32(acc[0][j], aw[0][0], bv.x, bv.y);
            mma_tf32(acc[1][j], aw[1][0], bv.x, bv.y);
            mma_tf32(acc[0][j], aw[0][1], bv.z, bv.w);
            mma_tf32(acc[1][j], aw[1][1], bv.z, bv.w);
        }

        if (kt + STAGES - 1 < KTILES) {
            int ns = stg + STAGES - 1;
            if (ns >= STAGES) ns -= STAGES;
            issue_copy(kt + STAGES - 1, ns);
        }
        asm volatile("cp.async.commit_group;" ::: "memory");
        if (++stg == STAGES) stg = 0;
    }

    // ---- epilogue: bias + float2 stores ----
    const int eg = lane >> 2, et = lane & 3;
    #pragma unroll
    for (int i = 0; i < 2; ++i) {
        const int cout0 = by * BM + wm * 32 + i * 16 + eg;
        const float bz0 = bias[cout0];
        const float bz1 = bias[cout0 + 8];
        #pragma unroll
        for (int j = 0; j < 8; ++j) {
            const int pj  = bx * BN + wn * 64 + j * 8;       // 8-aligned, HW%8==0
            const int n2  = pj / HW;
            const int hw2 = pj - n2 * HW + et * 2;
            float2 v0 = make_float2(acc[i][j][0] + bz0, acc[i][j][1] + bz0);
            float2 v1 = make_float2(acc[i][j][2] + bz1, acc[i][j][3] + bz1);
            *reinterpret_cast<float2*>(out + ((size_t)(n2 * C_OUT + cout0))     * HW + hw2) = v0;
            *reinterpret_cast<float2*>(out + ((size_t)(n2 * C_OUT + cout0 + 8)) * HW + hw2) = v1;
        }
    }
}

extern "C" void kernel_launch(void* const* d_in, const int* in_sizes, int n_in,
                              void* d_out, int out_size) {
    const float* in   = (const float*)d_in[0];
    const float* fl   = (const float*)d_in[1];
    const float* bias = (const float*)d_in[2];
    float* out        = (float*)d_out;

    cudaFuncSetAttribute(conv_mma, cudaFuncAttributeMaxDynamicSharedMemorySize, SMEM_BYTES);

    twa<<<(2*KTILES*512*4 + 255) / 256, 256>>>(fl);
    dim3 tg(HW / 32, C_IN / 32, 32);
    tin<<<tg, dim3(32, 8)>>>(in);
    dim3 grid(NPIX / BN, C_OUT / BM);
    conv_mma<<<grid, TPB, SMEM_BYTES>>>(bias, out);
}